// round 7
// baseline (speedup 1.0000x reference)
#include <cuda_runtime.h>

// Problem constants
#define Bx 8
#define Lx 256
#define Dx 256
#define BLD (Bx*Lx*Dx)   // 524288
#define BLL (Bx*Lx*Lx)   // 524288

typedef unsigned long long u64;

// Scratch (device globals — no allocation allowed)
__device__ float g_A[BLD],  g_Bm[BLD],  g_H[BLD];
__device__ float g_A2[BLD], g_Bm2[BLD], g_H2[BLD];   // K-split partials
__device__ float g_W[BLL];                            // softmax weights
__device__ float g_P1[BLD], g_P2[BLD];                // agg K-split partials

// ---- packed f32x2 helpers (Blackwell) --------------------------------------
__device__ __forceinline__ u64 pack2(float lo, float hi) {
    u64 r; asm("mov.b64 %0,{%1,%2};" : "=l"(r) : "f"(lo), "f"(hi)); return r;
}
__device__ __forceinline__ void unpack2(u64 v, float& lo, float& hi) {
    asm("mov.b64 {%0,%1},%2;" : "=f"(lo), "=f"(hi) : "l"(v));
}
__device__ __forceinline__ u64 ffma2(u64 a, u64 b, u64 c) {
    u64 d; asm("fma.rn.f32x2 %0,%1,%2,%3;" : "=l"(d) : "l"(a), "l"(b), "l"(c)); return d;
}
__device__ __forceinline__ u64 fadd2(u64 a, u64 b) {
    u64 d; asm("add.rn.f32x2 %0,%1,%2;" : "=l"(d) : "l"(a), "l"(b)); return d;
}
__device__ __forceinline__ u64 fmax2z(u64 a) {   // packed relu (2 scalar FMNMX;
    float lo, hi;                                 // movs fold to reg renaming)
    unpack2(a, lo, hi);
    return pack2(fmaxf(lo, 0.f), fmaxf(hi, 0.f));
}

// ---------------------------------------------------------------------------
// Kernel 1: projections, K-split x2. C[m,n] = sum_k X[m,k]*W[n,k] (NT GEMM)
// BM=64, BN=128, BK=16 (8 tiles per K-half), 128 threads, 8m x 8n per thread.
// acc packed along m: X operand = natural LDS.128 pairs (no duplication);
// W operand duplicated in registers (alu movs). 1 byte of LDS per FMA.
// grid (32, 2, 6): z>>1 = matrix, z&1 = K-half.
// ---------------------------------------------------------------------------
__global__ __launch_bounds__(128, 1) void proj_kernel(
    const float* __restrict__ Q,
    const float* __restrict__ Wa,
    const float* __restrict__ Wb,
    const float* __restrict__ Wd)
{
    int mat = blockIdx.z >> 1;
    int kh  = blockIdx.z & 1;
    const float* W = (mat == 0) ? Wa : (mat == 1) ? Wb : Wd;
    float* Out = (mat == 0) ? (kh ? g_A2 : g_A)
               : (mat == 1) ? (kh ? g_Bm2 : g_Bm)
                            : (kh ? g_H2 : g_H);

    __shared__ __align__(16) float Xs[2][16][68];    // [k][m]
    __shared__ __align__(16) float Ws[2][16][132];   // [k][n]

    int tid = threadIdx.x;
    int m0 = blockIdx.x * 64, n0 = blockIdx.y * 128;
    int ty = tid >> 4;          // 0..7  -> 8 m-rows
    int tx = tid & 15;          // 0..15 -> 8 n-cols
    int xr = tid & 63;          // X staging row
    int xk8 = (tid >> 6) * 8;   // 0 or 8
    int kbase = kh * 128;

    const float* xg = Q + (m0 + xr) * Dx + kbase + xk8;
    const float* wg = W + (n0 + tid) * Dx + kbase;

    float4 xa = *(const float4*)xg;
    float4 xb = *(const float4*)(xg + 4);
    float4 w0 = *(const float4*)wg;
    float4 w1 = *(const float4*)(wg + 4);
    float4 w2v = *(const float4*)(wg + 8);
    float4 w3 = *(const float4*)(wg + 12);
    {
        float xc[8] = {xa.x, xa.y, xa.z, xa.w, xb.x, xb.y, xb.z, xb.w};
#pragma unroll
        for (int q = 0; q < 8; q++) Xs[0][xk8 + q][xr] = xc[q];
        float wc[16] = {w0.x, w0.y, w0.z, w0.w, w1.x, w1.y, w1.z, w1.w,
                        w2v.x, w2v.y, w2v.z, w2v.w, w3.x, w3.y, w3.z, w3.w};
#pragma unroll
        for (int q = 0; q < 16; q++) Ws[0][q][tid] = wc[q];
    }
    __syncthreads();

    u64 acc[4][8];   // [m-pair][n]
#pragma unroll
    for (int p = 0; p < 4; p++)
#pragma unroll
        for (int n = 0; n < 8; n++) acc[p][n] = 0ull;

#pragma unroll 1
    for (int it = 0; it < 8; it++) {
        int buf = it & 1;
        if (it < 7) {
            int ko = (it + 1) * 16;
            xa = *(const float4*)(xg + ko);
            xb = *(const float4*)(xg + ko + 4);
            w0 = *(const float4*)(wg + ko);
            w1 = *(const float4*)(wg + ko + 4);
            w2v = *(const float4*)(wg + ko + 8);
            w3 = *(const float4*)(wg + ko + 12);
        }
#pragma unroll
        for (int kk = 0; kk < 16; kk++) {
            ulonglong2 x01 = *(const ulonglong2*)&Xs[buf][kk][ty * 8];
            ulonglong2 x23 = *(const ulonglong2*)&Xs[buf][kk][ty * 8 + 4];
            float4 wA = *(const float4*)&Ws[buf][kk][tx * 8];
            float4 wB = *(const float4*)&Ws[buf][kk][tx * 8 + 4];
            u64 xp[4] = {x01.x, x01.y, x23.x, x23.y};
            u64 wd[8];
            wd[0] = pack2(wA.x, wA.x); wd[1] = pack2(wA.y, wA.y);
            wd[2] = pack2(wA.z, wA.z); wd[3] = pack2(wA.w, wA.w);
            wd[4] = pack2(wB.x, wB.x); wd[5] = pack2(wB.y, wB.y);
            wd[6] = pack2(wB.z, wB.z); wd[7] = pack2(wB.w, wB.w);
#pragma unroll
            for (int n = 0; n < 8; n++)
#pragma unroll
                for (int p = 0; p < 4; p++)
                    acc[p][n] = ffma2(xp[p], wd[n], acc[p][n]);
        }
        if (it < 7) {
            int nb = buf ^ 1;
            float xc[8] = {xa.x, xa.y, xa.z, xa.w, xb.x, xb.y, xb.z, xb.w};
#pragma unroll
            for (int q = 0; q < 8; q++) Xs[nb][xk8 + q][xr] = xc[q];
            float wc[16] = {w0.x, w0.y, w0.z, w0.w, w1.x, w1.y, w1.z, w1.w,
                            w2v.x, w2v.y, w2v.z, w2v.w, w3.x, w3.y, w3.z, w3.w};
#pragma unroll
            for (int q = 0; q < 16; q++) Ws[nb][q][tid] = wc[q];
            __syncthreads();
        }
    }

    // acc[p][n] = (C[m=ty*8+2p], C[m=ty*8+2p+1]) at column n0+tx*8+n
#pragma unroll
    for (int p = 0; p < 4; p++) {
        float lo[8], hi[8];
#pragma unroll
        for (int n = 0; n < 8; n++) unpack2(acc[p][n], lo[n], hi[n]);
        float* d0 = Out + (m0 + ty * 8 + 2 * p) * Dx + n0 + tx * 8;
        float* d1 = d0 + Dx;
        *(float4*)(d0)     = make_float4(lo[0], lo[1], lo[2], lo[3]);
        *(float4*)(d0 + 4) = make_float4(lo[4], lo[5], lo[6], lo[7]);
        *(float4*)(d1)     = make_float4(hi[0], hi[1], hi[2], hi[3]);
        *(float4*)(d1 + 4) = make_float4(hi[4], hi[5], hi[6], hi[7]);
    }
}

// ---------------------------------------------------------------------------
// Combine K-split halves: g_A += g_A2, g_Bm += g_Bm2, g_H += g_H2.
// ---------------------------------------------------------------------------
__global__ __launch_bounds__(256) void combine_kernel()
{
    int idx = blockIdx.x * 256 + threadIdx.x;   // 0 .. BLD/4-1
    int arr = blockIdx.y;
    float4* d; const float4* s;
    if (arr == 0)      { d = (float4*)g_A;  s = (const float4*)g_A2;  }
    else if (arr == 1) { d = (float4*)g_Bm; s = (const float4*)g_Bm2; }
    else               { d = (float4*)g_H;  s = (const float4*)g_H2;  }
    float4 a = d[idx], b = s[idx];
    d[idx] = make_float4(a.x + b.x, a.y + b.y, a.z + b.z, a.w + b.w);
}

// ---------------------------------------------------------------------------
// Kernel 2: edge scores + mask + softmax -> g_W.
// Block = (b, 8 rows), 256 threads = 8 warps. Warp w: j-half jh=w>>2,
// rows r0=2*(w&3), r1=r0+1; lane jl covers j = jh*128 + gp*64 + jl*2.
// Softmax merged across j-half warps via smem.
// ---------------------------------------------------------------------------
__global__ __launch_bounds__(256) void edge_kernel(
    const int* __restrict__ dep,
    const float* __restrict__ w2)
{
    int b  = blockIdx.y;
    int i0 = blockIdx.x * 8;

    __shared__ __align__(16) float Ash2[8][520];    // A rows, dup pairs
    __shared__ __align__(16) float w2d[512];        // w2 dup pairs
    __shared__ __align__(16) float Bt[2][16][258];  // [cl][j] transposed
    __shared__ float redmx[2][8], redsum[2][8];

    int tid = threadIdx.x;

    // stage 8 A rows duplicated
#pragma unroll
    for (int p = 0; p < 2; p++) {
        int e = tid * 4 + p * 1024;
        int il = e >> 8, c = e & 255;
        float4 v = *(const float4*)(g_A + (b * Lx + i0 + il) * Dx + c);
        *(u64*)&Ash2[il][2 * c]     = pack2(v.x, v.x);
        *(u64*)&Ash2[il][2 * c + 2] = pack2(v.y, v.y);
        *(u64*)&Ash2[il][2 * c + 4] = pack2(v.z, v.z);
        *(u64*)&Ash2[il][2 * c + 6] = pack2(v.w, v.w);
    }
    {
        float v = w2[tid];
        *(u64*)&w2d[2 * tid] = pack2(v, v);
    }

    const float* Bbase = g_Bm + b * Lx * Dx;

    float4 pf[4];
#pragma unroll
    for (int p = 0; p < 4; p++) {
        int e = tid * 4 + p * 1024;
        int j = e >> 4, cl = e & 15;
        pf[p] = *(const float4*)(Bbase + j * Dx + cl);
    }
#pragma unroll
    for (int p = 0; p < 4; p++) {
        int e = tid * 4 + p * 1024;
        int j = e >> 4, cl = e & 15;
        Bt[0][cl + 0][j] = pf[p].x; Bt[0][cl + 1][j] = pf[p].y;
        Bt[0][cl + 2][j] = pf[p].z; Bt[0][cl + 3][j] = pf[p].w;
    }
    __syncthreads();

    int w  = tid >> 5;
    int jl = tid & 31;
    int jh = w >> 2;           // j-half 0/1
    int wr = w & 3;            // row pair
    int r0 = wr * 2, r1 = r0 + 1;
    int jbase = jh * 128;

    u64 acc0[2] = {0, 0}, acc1[2] = {0, 0};

#pragma unroll 1
    for (int ch = 0; ch < 16; ch++) {
        int buf = ch & 1;
        if (ch < 15) {
            int c0 = (ch + 1) * 16;
#pragma unroll
            for (int p = 0; p < 4; p++) {
                int e = tid * 4 + p * 1024;
                int j = e >> 4, cl = e & 15;
                pf[p] = *(const float4*)(Bbase + j * Dx + c0 + cl);
            }
        }
#pragma unroll
        for (int c2 = 0; c2 < 8; c2++) {
            int cbase = ch * 16 + c2 * 2;
            ulonglong2 A0 = *(const ulonglong2*)&Ash2[r0][cbase * 2];
            ulonglong2 A1 = *(const ulonglong2*)&Ash2[r1][cbase * 2];
            ulonglong2 UU = *(const ulonglong2*)&w2d[cbase * 2];
#pragma unroll
            for (int cc = 0; cc < 2; cc++) {
                u64 a0 = cc ? A0.y : A0.x;
                u64 a1 = cc ? A1.y : A1.x;
                u64 up = cc ? UU.y : UU.x;
                int cl = c2 * 2 + cc;
#pragma unroll
                for (int gp = 0; gp < 2; gp++) {
                    u64 bt = *(const u64*)&Bt[buf][cl][jbase + gp * 64 + jl * 2];
                    acc0[gp] = ffma2(fmax2z(fadd2(a0, bt)), up, acc0[gp]);
                    acc1[gp] = ffma2(fmax2z(fadd2(a1, bt)), up, acc1[gp]);
                }
            }
        }
        if (ch < 15) {
            int nb = buf ^ 1;
#pragma unroll
            for (int p = 0; p < 4; p++) {
                int e = tid * 4 + p * 1024;
                int j = e >> 4, cl = e & 15;
                Bt[nb][cl + 0][j] = pf[p].x; Bt[nb][cl + 1][j] = pf[p].y;
                Bt[nb][cl + 2][j] = pf[p].z; Bt[nb][cl + 3][j] = pf[p].w;
            }
            __syncthreads();
        }
    }

    // ---- masked softmax, merged across the two j-half warps ----
    int gi0 = b * Lx + i0 + r0;
    int gi1 = b * Lx + i0 + r1;
    float T0[4], T1[4];
    int   mk0[4], mk1[4];
    float mx0 = -1e30f, mx1 = -1e30f;
#pragma unroll
    for (int gp = 0; gp < 2; gp++) {
        int j0 = jbase + gp * 64 + jl * 2;
        int2 m0v = *(const int2*)(dep + gi0 * Lx + j0);
        int2 m1v = *(const int2*)(dep + gi1 * Lx + j0);
        float lo, hi;
        unpack2(acc0[gp], lo, hi);
        mk0[2*gp]   = (m0v.x > 0);
        mk0[2*gp+1] = (m0v.y > 0);
        T0[2*gp]    = mk0[2*gp]   ? lo : -100.0f;
        T0[2*gp+1]  = mk0[2*gp+1] ? hi : -100.0f;
        unpack2(acc1[gp], lo, hi);
        mk1[2*gp]   = (m1v.x > 0);
        mk1[2*gp+1] = (m1v.y > 0);
        T1[2*gp]    = mk1[2*gp]   ? lo : -100.0f;
        T1[2*gp+1]  = mk1[2*gp+1] ? hi : -100.0f;
        mx0 = fmaxf(mx0, fmaxf(T0[2*gp], T0[2*gp+1]));
        mx1 = fmaxf(mx1, fmaxf(T1[2*gp], T1[2*gp+1]));
    }
#pragma unroll
    for (int off = 16; off > 0; off >>= 1) {
        mx0 = fmaxf(mx0, __shfl_xor_sync(0xffffffffu, mx0, off));
        mx1 = fmaxf(mx1, __shfl_xor_sync(0xffffffffu, mx1, off));
    }
    if (jl == 0) { redmx[jh][r0] = mx0; redmx[jh][r1] = mx1; }
    __syncthreads();
    float gmx0 = fmaxf(redmx[0][r0], redmx[1][r0]);
    float gmx1 = fmaxf(redmx[0][r1], redmx[1][r1]);

    float E0[4], E1[4], sum0 = 0.f, sum1 = 0.f;
#pragma unroll
    for (int g = 0; g < 4; g++) {
        E0[g] = expf(T0[g] - gmx0); sum0 += E0[g];
        E1[g] = expf(T1[g] - gmx1); sum1 += E1[g];
    }
#pragma unroll
    for (int off = 16; off > 0; off >>= 1) {
        sum0 += __shfl_xor_sync(0xffffffffu, sum0, off);
        sum1 += __shfl_xor_sync(0xffffffffu, sum1, off);
    }
    if (jl == 0) { redsum[jh][r0] = sum0; redsum[jh][r1] = sum1; }
    __syncthreads();
    float inv0 = 1.0f / (redsum[0][r0] + redsum[1][r0]);
    float inv1 = 1.0f / (redsum[0][r1] + redsum[1][r1]);

#pragma unroll
    for (int gp = 0; gp < 2; gp++) {
        int j0 = jbase + gp * 64 + jl * 2;
        float2 o0, o1;
        o0.x = mk0[2*gp]   ? E0[2*gp]   * inv0 : 0.f;
        o0.y = mk0[2*gp+1] ? E0[2*gp+1] * inv0 : 0.f;
        o1.x = mk1[2*gp]   ? E1[2*gp]   * inv1 : 0.f;
        o1.y = mk1[2*gp+1] ? E1[2*gp+1] * inv1 : 0.f;
        *(float2*)(g_W + gi0 * Lx + j0) = o0;
        *(float2*)(g_W + gi1 * Lx + j0) = o1;
    }
}

// ---------------------------------------------------------------------------
// Kernel 3: agg partials, K-split x2 over j. P[i,c] = sum_j w[i,j] H[j,c].
// BM=32, BN=128, BK=16, 128 threads, 4i x 8c per thread (acc packed along c:
// H natural pairs, W duplicated in registers). grid (8, 2, 16) = 256 blocks.
// ---------------------------------------------------------------------------
__global__ __launch_bounds__(128, 1) void agg_kernel()
{
    int b  = blockIdx.z >> 1;
    int kh = blockIdx.z & 1;
    int i0 = blockIdx.x * 32;
    int c0 = blockIdx.y * 128;
    int jb = kh * 128;

    __shared__ __align__(16) float Wt[2][16][36];   // [k][i]
    __shared__ __align__(16) float Hs[2][16][132];  // [k][c]

    int tid = threadIdx.x;
    int ty = tid >> 4;          // 0..7  -> 4 i each
    int tx = tid & 15;          // 0..15 -> 8 c each
    int wr = tid & 31;          // W staging row
    int wk4 = (tid >> 5) * 4;   // 0,4,8,12
    int hj = tid >> 3;          // 0..15
    int hc = (tid & 7) * 16;    // 0..112

    const float* Wg = g_W + (b * Lx + i0 + wr) * Lx + jb + wk4;
    const float* Hg = g_H + (b * Lx + jb + hj) * Dx + c0 + hc;

    float4 wv = *(const float4*)Wg;
    float4 hv[4];
#pragma unroll
    for (int u = 0; u < 4; u++) hv[u] = *(const float4*)(Hg + u * 4);
    {
        float wc[4] = {wv.x, wv.y, wv.z, wv.w};
#pragma unroll
        for (int q = 0; q < 4; q++) Wt[0][wk4 + q][wr] = wc[q];
#pragma unroll
        for (int u = 0; u < 4; u++) *(float4*)&Hs[0][hj][hc + u * 4] = hv[u];
    }
    __syncthreads();

    u64 acc[4][4];   // [i][c-pair]
#pragma unroll
    for (int i = 0; i < 4; i++)
#pragma unroll
        for (int n = 0; n < 4; n++) acc[i][n] = 0ull;

#pragma unroll 1
    for (int it = 0; it < 8; it++) {
        int buf = it & 1;
        if (it < 7) {
            wv = *(const float4*)(Wg + (it + 1) * 16);
#pragma unroll
            for (int u = 0; u < 4; u++)
                hv[u] = *(const float4*)(Hg + (it + 1) * 16 * Dx + u * 4);
        }
#pragma unroll
        for (int kk = 0; kk < 16; kk++) {
            float4 w4 = *(const float4*)&Wt[buf][kk][ty * 4];
            u64 wd[4];
            wd[0] = pack2(w4.x, w4.x); wd[1] = pack2(w4.y, w4.y);
            wd[2] = pack2(w4.z, w4.z); wd[3] = pack2(w4.w, w4.w);
            ulonglong2 h01 = *(const ulonglong2*)&Hs[buf][kk][tx * 8];
            ulonglong2 h23 = *(const ulonglong2*)&Hs[buf][kk][tx * 8 + 4];
            u64 hp[4] = {h01.x, h01.y, h23.x, h23.y};
#pragma unroll
            for (int i = 0; i < 4; i++)
#pragma unroll
                for (int n = 0; n < 4; n++)
                    acc[i][n] = ffma2(wd[i], hp[n], acc[i][n]);
        }
        if (it < 7) {
            int nb = buf ^ 1;
            float wc[4] = {wv.x, wv.y, wv.z, wv.w};
#pragma unroll
            for (int q = 0; q < 4; q++) Wt[nb][wk4 + q][wr] = wc[q];
#pragma unroll
            for (int u = 0; u < 4; u++) *(float4*)&Hs[nb][hj][hc + u * 4] = hv[u];
            __syncthreads();
        }
    }

    float* P = kh ? g_P2 : g_P1;
#pragma unroll
    for (int i = 0; i < 4; i++) {
        int row = i0 + ty * 4 + i;
        float* d = P + (b * Lx + row) * Dx + c0 + tx * 8;
        ulonglong2 o1, o2;
        o1.x = acc[i][0]; o1.y = acc[i][1];
        o2.x = acc[i][2]; o2.y = acc[i][3];
        *(ulonglong2*)(d)     = o1;
        *(ulonglong2*)(d + 4) = o2;
    }
}

// ---------------------------------------------------------------------------
// Finish: out = relu(Q + P1 + P2); tail casts for wordlens + syntactic_dep.
// ---------------------------------------------------------------------------
__global__ __launch_bounds__(256) void finish_kernel(
    const float* __restrict__ Q,
    const int* __restrict__ wl,
    const int* __restrict__ dep,
    float* __restrict__ out)
{
    int idx = blockIdx.x * 256 + threadIdx.x;
    if (blockIdx.y == 0) {
        float4 q  = ((const float4*)Q)[idx];
        float4 p1 = ((const float4*)g_P1)[idx];
        float4 p2 = ((const float4*)g_P2)[idx];
        ((float4*)out)[idx] = make_float4(
            fmaxf(q.x + p1.x + p2.x, 0.f), fmaxf(q.y + p1.y + p2.y, 0.f),
            fmaxf(q.z + p1.z + p2.z, 0.f), fmaxf(q.w + p1.w + p2.w, 0.f));
    } else {
        int4 d = ((const int4*)dep)[idx];
        ((float4*)(out + BLD + Bx))[idx] =
            make_float4((float)d.x, (float)d.y, (float)d.z, (float)d.w);
        if (blockIdx.x == 0 && threadIdx.x < Bx)
            out[BLD + threadIdx.x] = (float)wl[threadIdx.x];
    }
}

// ---------------------------------------------------------------------------
extern "C" void kernel_launch(void* const* d_in, const int* in_sizes, int n_in,
                              void* d_out, int out_size)
{
    const float* Q   = (const float*)d_in[0];
    const int*   wl  = (const int*)d_in[1];
    const int*   dep = (const int*)d_in[2];
    const float* Wa  = (const float*)d_in[3];
    const float* Wb  = (const float*)d_in[4];
    const float* w2  = (const float*)d_in[5];
    const float* Wd  = (const float*)d_in[6];
    float* out = (float*)d_out;

    bool tail = (out_size >= BLD + Bx + BLL);

    // projections, K-split x2 (384 blocks x 128 thr)
    proj_kernel<<<dim3(32, 2, 6), 128>>>(Q, Wa, Wb, Wd);
    // combine halves (1536 tiny blocks)
    combine_kernel<<<dim3(BLD / 4 / 256, 3), 256>>>();
    // edge scores + softmax -> g_W (256 blocks x 256 thr)
    edge_kernel<<<dim3(32, Bx), 256>>>(dep, w2);
    // aggregation partials, K-split x2 (256 blocks x 128 thr)
    agg_kernel<<<dim3(8, 2, 16), 128>>>();
    // residual relu + tail casts
    finish_kernel<<<dim3(512, tail ? 2 : 1), 256>>>(Q, wl, dep, out);
}

// round 8
// speedup vs baseline: 1.7988x; 1.7988x over previous
#include <cuda_runtime.h>

// Problem constants
#define Bx 8
#define Lx 256
#define Dx 256
#define BLD (Bx*Lx*Dx)   // 524288
#define BLL (Bx*Lx*Lx)   // 524288

typedef unsigned int u32;
typedef unsigned long long u64;

// Scratch (device globals — no allocation allowed)
__device__ float g_A[BLD], g_Bm[BLD], g_H[BLD];
__device__ float g_W[BLL];

// ---- tf32 mma helpers ------------------------------------------------------
__device__ __forceinline__ u32 f2tf(float x) {
    u32 r; asm("cvt.rna.tf32.f32 %0,%1;" : "=r"(r) : "f"(x)); return r;
}
__device__ __forceinline__ void mma_tf32(float c[4], const u32 a[4], const u32 b[2]) {
    asm volatile(
        "mma.sync.aligned.m16n8k8.row.col.f32.tf32.tf32.f32 "
        "{%0,%1,%2,%3},{%4,%5,%6,%7},{%8,%9},{%0,%1,%2,%3};"
        : "+f"(c[0]), "+f"(c[1]), "+f"(c[2]), "+f"(c[3])
        : "r"(a[0]), "r"(a[1]), "r"(a[2]), "r"(a[3]), "r"(b[0]), "r"(b[1]));
}

// ---- packed f32x2 helpers (edge kernel) ------------------------------------
__device__ __forceinline__ u64 pack2(float lo, float hi) {
    u64 r; asm("mov.b64 %0,{%1,%2};" : "=l"(r) : "f"(lo), "f"(hi)); return r;
}
__device__ __forceinline__ void unpack2(u64 v, float& lo, float& hi) {
    asm("mov.b64 {%0,%1},%2;" : "=f"(lo), "=f"(hi) : "l"(v));
}
__device__ __forceinline__ u64 ffma2(u64 a, u64 b, u64 c) {
    u64 d; asm("fma.rn.f32x2 %0,%1,%2,%3;" : "=l"(d) : "l"(a), "l"(b), "l"(c)); return d;
}
__device__ __forceinline__ u64 fadd2(u64 a, u64 b) {
    u64 d; asm("add.rn.f32x2 %0,%1,%2;" : "=l"(d) : "l"(a), "l"(b)); return d;
}
__device__ __forceinline__ u64 fmax2z(u64 a) {
    float lo, hi; unpack2(a, lo, hi);
    return pack2(fmaxf(lo, 0.f), fmaxf(hi, 0.f));
}

// ---------------------------------------------------------------------------
// Kernel 1: projections via tf32 HMMA. C[m,n] = sum_k X[m,k]*W[n,k] (NT).
// Block 64m x 64n, 256 thr = 8 warps (2m x 4n), warp tile 32x16.
// Xs/Ws staged tf32-converted, [k][row] layout, strides 136/72 (≡8 mod 32:
// fragment loads conflict-free; staging stores lane-linear, conflict-free).
// grid (32, 4, 3) = 384 blocks.
// ---------------------------------------------------------------------------
__global__ __launch_bounds__(256) void proj_kernel(
    const float* __restrict__ Q,
    const float* __restrict__ Wa,
    const float* __restrict__ Wb,
    const float* __restrict__ Wd)
{
    int mat = blockIdx.z;
    const float* W = (mat == 0) ? Wa : (mat == 1) ? Wb : Wd;
    float* Out     = (mat == 0) ? g_A : (mat == 1) ? g_Bm : g_H;

    __shared__ u32 Xs[2][16][136];   // [k][m], 64 m
    __shared__ u32 Ws[2][16][72];    // [k][n], 64 n

    int tid  = threadIdx.x;
    int m0 = blockIdx.x * 64, n0 = blockIdx.y * 64;
    int wid = tid >> 5, lane = tid & 31;
    int wm = wid & 1;        // 2 m-halves of 32
    int wn = wid >> 1;       // 4 n-quarters of 16
    int lg = lane >> 2, lk = lane & 3;

    int sr  = tid & 63;          // staging row (m or n)
    int sk4 = (tid >> 6) * 4;    // staging k base (0,4,8,12)

    const float* xg = Q + (m0 + sr) * Dx + sk4;
    const float* wg = W + (n0 + sr) * Dx + sk4;

    float4 xv = *(const float4*)xg;
    float4 wv = *(const float4*)wg;
    Xs[0][sk4 + 0][sr] = f2tf(xv.x); Xs[0][sk4 + 1][sr] = f2tf(xv.y);
    Xs[0][sk4 + 2][sr] = f2tf(xv.z); Xs[0][sk4 + 3][sr] = f2tf(xv.w);
    Ws[0][sk4 + 0][sr] = f2tf(wv.x); Ws[0][sk4 + 1][sr] = f2tf(wv.y);
    Ws[0][sk4 + 2][sr] = f2tf(wv.z); Ws[0][sk4 + 3][sr] = f2tf(wv.w);
    __syncthreads();

    float c[2][2][4];   // [mt][nt][frag]
#pragma unroll
    for (int mt = 0; mt < 2; mt++)
#pragma unroll
        for (int nt = 0; nt < 2; nt++)
#pragma unroll
            for (int q = 0; q < 4; q++) c[mt][nt][q] = 0.f;

#pragma unroll 1
    for (int it = 0; it < 16; it++) {
        int buf = it & 1;
        if (it < 15) {
            xv = *(const float4*)(xg + (it + 1) * 16);
            wv = *(const float4*)(wg + (it + 1) * 16);
        }
#pragma unroll
        for (int ks = 0; ks < 2; ks++) {
            int kc = ks * 8;
            u32 a[2][4], bfr[2][2];
#pragma unroll
            for (int mt = 0; mt < 2; mt++) {
                int mb = wm * 32 + mt * 16;
                a[mt][0] = Xs[buf][kc + lk][mb + lg];
                a[mt][1] = Xs[buf][kc + lk][mb + lg + 8];
                a[mt][2] = Xs[buf][kc + 4 + lk][mb + lg];
                a[mt][3] = Xs[buf][kc + 4 + lk][mb + lg + 8];
            }
#pragma unroll
            for (int nt = 0; nt < 2; nt++) {
                int nb = wn * 16 + nt * 8;
                bfr[nt][0] = Ws[buf][kc + lk][nb + lg];
                bfr[nt][1] = Ws[buf][kc + 4 + lk][nb + lg];
            }
#pragma unroll
            for (int mt = 0; mt < 2; mt++)
#pragma unroll
                for (int nt = 0; nt < 2; nt++)
                    mma_tf32(c[mt][nt], a[mt], bfr[nt]);
        }
        if (it < 15) {
            int nb = buf ^ 1;
            Xs[nb][sk4 + 0][sr] = f2tf(xv.x); Xs[nb][sk4 + 1][sr] = f2tf(xv.y);
            Xs[nb][sk4 + 2][sr] = f2tf(xv.z); Xs[nb][sk4 + 3][sr] = f2tf(xv.w);
            Ws[nb][sk4 + 0][sr] = f2tf(wv.x); Ws[nb][sk4 + 1][sr] = f2tf(wv.y);
            Ws[nb][sk4 + 2][sr] = f2tf(wv.z); Ws[nb][sk4 + 3][sr] = f2tf(wv.w);
            __syncthreads();
        }
    }

#pragma unroll
    for (int mt = 0; mt < 2; mt++) {
        int row = m0 + wm * 32 + mt * 16 + lg;
#pragma unroll
        for (int nt = 0; nt < 2; nt++) {
            int col = n0 + wn * 16 + nt * 8 + 2 * lk;
            *(float2*)(Out + row * Dx + col)       = make_float2(c[mt][nt][0], c[mt][nt][1]);
            *(float2*)(Out + (row + 8) * Dx + col) = make_float2(c[mt][nt][2], c[mt][nt][3]);
        }
    }
}

// ---------------------------------------------------------------------------
// Kernel 2: edge scores + mask + softmax -> g_W, tail casts folded in (R5).
// Block = (b, 8 rows), 256 threads = 8 warps; warp = (j-half, row-pair).
// ---------------------------------------------------------------------------
__global__ __launch_bounds__(256) void edge_kernel(
    const int* __restrict__ dep,
    const float* __restrict__ w2,
    const int* __restrict__ wl,
    float* __restrict__ dst)   // out + BLD, or nullptr
{
    int b  = blockIdx.y;
    int i0 = blockIdx.x * 8;

    __shared__ __align__(16) float Ash2[8][520];
    __shared__ __align__(16) float w2d[512];
    __shared__ __align__(16) float Bt[2][16][258];
    __shared__ float redmx[2][8], redsum[2][8];

    int tid = threadIdx.x;

#pragma unroll
    for (int p = 0; p < 2; p++) {
        int e = tid * 4 + p * 1024;
        int il = e >> 8, cc = e & 255;
        float4 v = *(const float4*)(g_A + (b * Lx + i0 + il) * Dx + cc);
        *(u64*)&Ash2[il][2 * cc]     = pack2(v.x, v.x);
        *(u64*)&Ash2[il][2 * cc + 2] = pack2(v.y, v.y);
        *(u64*)&Ash2[il][2 * cc + 4] = pack2(v.z, v.z);
        *(u64*)&Ash2[il][2 * cc + 6] = pack2(v.w, v.w);
    }
    {
        float v = w2[tid];
        *(u64*)&w2d[2 * tid] = pack2(v, v);
    }
    if (dst && blockIdx.x == 0 && blockIdx.y == 0 && tid < Bx)
        dst[tid] = (float)wl[tid];
    float* depout = dst ? dst + Bx : nullptr;

    const float* Bbase = g_Bm + b * Lx * Dx;

    float4 pf[4];
#pragma unroll
    for (int p = 0; p < 4; p++) {
        int e = tid * 4 + p * 1024;
        int j = e >> 4, cl = e & 15;
        pf[p] = *(const float4*)(Bbase + j * Dx + cl);
    }
#pragma unroll
    for (int p = 0; p < 4; p++) {
        int e = tid * 4 + p * 1024;
        int j = e >> 4, cl = e & 15;
        Bt[0][cl + 0][j] = pf[p].x; Bt[0][cl + 1][j] = pf[p].y;
        Bt[0][cl + 2][j] = pf[p].z; Bt[0][cl + 3][j] = pf[p].w;
    }
    __syncthreads();

    int w  = tid >> 5;
    int jl = tid & 31;
    int jh = w >> 2;
    int wr = w & 3;
    int r0 = wr * 2, r1 = r0 + 1;
    int jbase = jh * 128;

    u64 acc0[2] = {0, 0}, acc1[2] = {0, 0};

#pragma unroll 1
    for (int ch = 0; ch < 16; ch++) {
        int buf = ch & 1;
        if (ch < 15) {
            int c0 = (ch + 1) * 16;
#pragma unroll
            for (int p = 0; p < 4; p++) {
                int e = tid * 4 + p * 1024;
                int j = e >> 4, cl = e & 15;
                pf[p] = *(const float4*)(Bbase + j * Dx + c0 + cl);
            }
        }
#pragma unroll
        for (int c2 = 0; c2 < 8; c2++) {
            int cbase = ch * 16 + c2 * 2;
            ulonglong2 A0 = *(const ulonglong2*)&Ash2[r0][cbase * 2];
            ulonglong2 A1 = *(const ulonglong2*)&Ash2[r1][cbase * 2];
            ulonglong2 UU = *(const ulonglong2*)&w2d[cbase * 2];
#pragma unroll
            for (int cc = 0; cc < 2; cc++) {
                u64 a0 = cc ? A0.y : A0.x;
                u64 a1 = cc ? A1.y : A1.x;
                u64 up = cc ? UU.y : UU.x;
                int cl = c2 * 2 + cc;
#pragma unroll
                for (int gp = 0; gp < 2; gp++) {
                    u64 bt = *(const u64*)&Bt[buf][cl][jbase + gp * 64 + jl * 2];
                    acc0[gp] = ffma2(fmax2z(fadd2(a0, bt)), up, acc0[gp]);
                    acc1[gp] = ffma2(fmax2z(fadd2(a1, bt)), up, acc1[gp]);
                }
            }
        }
        if (ch < 15) {
            int nb = buf ^ 1;
#pragma unroll
            for (int p = 0; p < 4; p++) {
                int e = tid * 4 + p * 1024;
                int j = e >> 4, cl = e & 15;
                Bt[nb][cl + 0][j] = pf[p].x; Bt[nb][cl + 1][j] = pf[p].y;
                Bt[nb][cl + 2][j] = pf[p].z; Bt[nb][cl + 3][j] = pf[p].w;
            }
            __syncthreads();
        }
    }

    int gi0 = b * Lx + i0 + r0;
    int gi1 = b * Lx + i0 + r1;
    float T0[4], T1[4];
    int   mk0[4], mk1[4];
    float mx0 = -1e30f, mx1 = -1e30f;
#pragma unroll
    for (int gp = 0; gp < 2; gp++) {
        int j0 = jbase + gp * 64 + jl * 2;
        int2 m0v = *(const int2*)(dep + gi0 * Lx + j0);
        int2 m1v = *(const int2*)(dep + gi1 * Lx + j0);
        float lo, hi;
        unpack2(acc0[gp], lo, hi);
        mk0[2*gp]   = (m0v.x > 0);
        mk0[2*gp+1] = (m0v.y > 0);
        T0[2*gp]    = mk0[2*gp]   ? lo : -100.0f;
        T0[2*gp+1]  = mk0[2*gp+1] ? hi : -100.0f;
        unpack2(acc1[gp], lo, hi);
        mk1[2*gp]   = (m1v.x > 0);
        mk1[2*gp+1] = (m1v.y > 0);
        T1[2*gp]    = mk1[2*gp]   ? lo : -100.0f;
        T1[2*gp+1]  = mk1[2*gp+1] ? hi : -100.0f;
        mx0 = fmaxf(mx0, fmaxf(T0[2*gp], T0[2*gp+1]));
        mx1 = fmaxf(mx1, fmaxf(T1[2*gp], T1[2*gp+1]));
        if (depout) {
            *(float2*)(depout + gi0 * Lx + j0) = make_float2((float)m0v.x, (float)m0v.y);
            *(float2*)(depout + gi1 * Lx + j0) = make_float2((float)m1v.x, (float)m1v.y);
        }
    }
#pragma unroll
    for (int off = 16; off > 0; off >>= 1) {
        mx0 = fmaxf(mx0, __shfl_xor_sync(0xffffffffu, mx0, off));
        mx1 = fmaxf(mx1, __shfl_xor_sync(0xffffffffu, mx1, off));
    }
    if (jl == 0) { redmx[jh][r0] = mx0; redmx[jh][r1] = mx1; }
    __syncthreads();
    float gmx0 = fmaxf(redmx[0][r0], redmx[1][r0]);
    float gmx1 = fmaxf(redmx[0][r1], redmx[1][r1]);

    float E0[4], E1[4], sum0 = 0.f, sum1 = 0.f;
#pragma unroll
    for (int g = 0; g < 4; g++) {
        E0[g] = expf(T0[g] - gmx0); sum0 += E0[g];
        E1[g] = expf(T1[g] - gmx1); sum1 += E1[g];
    }
#pragma unroll
    for (int off = 16; off > 0; off >>= 1) {
        sum0 += __shfl_xor_sync(0xffffffffu, sum0, off);
        sum1 += __shfl_xor_sync(0xffffffffu, sum1, off);
    }
    if (jl == 0) { redsum[jh][r0] = sum0; redsum[jh][r1] = sum1; }
    __syncthreads();
    float inv0 = 1.0f / (redsum[0][r0] + redsum[1][r0]);
    float inv1 = 1.0f / (redsum[0][r1] + redsum[1][r1]);

#pragma unroll
    for (int gp = 0; gp < 2; gp++) {
        int j0 = jbase + gp * 64 + jl * 2;
        float2 o0, o1;
        o0.x = mk0[2*gp]   ? E0[2*gp]   * inv0 : 0.f;
        o0.y = mk0[2*gp+1] ? E0[2*gp+1] * inv0 : 0.f;
        o1.x = mk1[2*gp]   ? E1[2*gp]   * inv1 : 0.f;
        o1.y = mk1[2*gp+1] ? E1[2*gp+1] * inv1 : 0.f;
        *(float2*)(g_W + gi0 * Lx + j0) = o0;
        *(float2*)(g_W + gi1 * Lx + j0) = o1;
    }
}

// ---------------------------------------------------------------------------
// Kernel 3: agg via tf32 HMMA + fused epilogue. out = relu(Q + w@H).
// Block 32i x 64c, 256 thr = 8 warps (2m16 x 4n16), warp tile 16x16.
// Wt [j][i] stride 40 (≡8 mod 32); Hs [c][j] stride 20 (fragment loads
// conflict-free). grid (8, 4, 8) = 256 blocks.
// ---------------------------------------------------------------------------
__global__ __launch_bounds__(256) void agg_kernel(
    const float* __restrict__ Q,
    float* __restrict__ out)
{
    int b  = blockIdx.z;
    int i0 = blockIdx.x * 32;
    int c0 = blockIdx.y * 64;

    __shared__ u32 Wt[2][16][40];   // [j][i], 32 i
    __shared__ u32 Hs[2][64][20];   // [c][j], 16 j

    int tid = threadIdx.x;
    int wid = tid >> 5, lane = tid & 31;
    int wm = wid & 1;        // which m16 of the 32 i-rows
    int wn = wid >> 1;       // 4 n-quarters of 16
    int lg = lane >> 2, lk = lane & 3;

    int si  = tid & 31;            // Wt staging i
    int sj2 = (tid >> 5) * 2;      // Wt staging j base (0..14 even)
    int hj  = tid & 15;            // Hs staging j
    int hc4 = (tid >> 4) * 4;      // Hs staging c base

    const float* Wg = g_W + (b * Lx + i0 + si) * Lx + sj2;
    const float* Hg = g_H + (b * Lx + hj) * Dx + c0 + hc4;

    float2 wv = *(const float2*)Wg;
    float4 hv = *(const float4*)Hg;
    Wt[0][sj2][si]     = f2tf(wv.x);
    Wt[0][sj2 + 1][si] = f2tf(wv.y);
    Hs[0][hc4 + 0][hj] = f2tf(hv.x); Hs[0][hc4 + 1][hj] = f2tf(hv.y);
    Hs[0][hc4 + 2][hj] = f2tf(hv.z); Hs[0][hc4 + 3][hj] = f2tf(hv.w);
    __syncthreads();

    float c[2][4];   // [nt][frag]
#pragma unroll
    for (int nt = 0; nt < 2; nt++)
#pragma unroll
        for (int q = 0; q < 4; q++) c[nt][q] = 0.f;

#pragma unroll 1
    for (int it = 0; it < 16; it++) {
        int buf = it & 1;
        if (it < 15) {
            wv = *(const float2*)(Wg + (it + 1) * 16);
            hv = *(const float4*)(Hg + (it + 1) * 16 * Dx);
        }
#pragma unroll
        for (int ks = 0; ks < 2; ks++) {
            int kc = ks * 8;
            u32 a[4], bfr[2][2];
            int mb = wm * 16;
            a[0] = Wt[buf][kc + lk][mb + lg];
            a[1] = Wt[buf][kc + lk][mb + lg + 8];
            a[2] = Wt[buf][kc + 4 + lk][mb + lg];
            a[3] = Wt[buf][kc + 4 + lk][mb + lg + 8];
#pragma unroll
            for (int nt = 0; nt < 2; nt++) {
                int cb = wn * 16 + nt * 8;
                bfr[nt][0] = Hs[buf][cb + lg][kc + lk];
                bfr[nt][1] = Hs[buf][cb + lg][kc + 4 + lk];
            }
#pragma unroll
            for (int nt = 0; nt < 2; nt++)
                mma_tf32(c[nt], a, bfr[nt]);
        }
        if (it < 15) {
            int nb = buf ^ 1;
            Wt[nb][sj2][si]     = f2tf(wv.x);
            Wt[nb][sj2 + 1][si] = f2tf(wv.y);
            Hs[nb][hc4 + 0][hj] = f2tf(hv.x); Hs[nb][hc4 + 1][hj] = f2tf(hv.y);
            Hs[nb][hc4 + 2][hj] = f2tf(hv.z); Hs[nb][hc4 + 3][hj] = f2tf(hv.w);
            __syncthreads();
        }
    }

#pragma unroll
    for (int nt = 0; nt < 2; nt++) {
        int col  = c0 + wn * 16 + nt * 8 + 2 * lk;
        int row0 = i0 + wm * 16 + lg;
        long base0 = (long)(b * Lx + row0) * Dx + col;
        long base1 = (long)(b * Lx + row0 + 8) * Dx + col;
        float2 q0 = *(const float2*)(Q + base0);
        float2 q1 = *(const float2*)(Q + base1);
        *(float2*)(out + base0) = make_float2(fmaxf(q0.x + c[nt][0], 0.f),
                                              fmaxf(q0.y + c[nt][1], 0.f));
        *(float2*)(out + base1) = make_float2(fmaxf(q1.x + c[nt][2], 0.f),
                                              fmaxf(q1.y + c[nt][3], 0.f));
    }
}

// ---------------------------------------------------------------------------
extern "C" void kernel_launch(void* const* d_in, const int* in_sizes, int n_in,
                              void* d_out, int out_size)
{
    const float* Q   = (const float*)d_in[0];
    const int*   wl  = (const int*)d_in[1];
    const int*   dep = (const int*)d_in[2];
    const float* Wa  = (const float*)d_in[3];
    const float* Wb  = (const float*)d_in[4];
    const float* w2  = (const float*)d_in[5];
    const float* Wd  = (const float*)d_in[6];
    float* out = (float*)d_out;

    float* dst = (out_size >= BLD + Bx + BLL) ? out + BLD : nullptr;

    // projections via tf32 HMMA (384 blocks x 256 thr)
    proj_kernel<<<dim3(32, 4, 3), 256>>>(Q, Wa, Wb, Wd);
    // edge scores + softmax -> g_W (+ tail casts) (256 blocks x 256 thr)
    edge_kernel<<<dim3(32, Bx), 256>>>(dep, w2, wl, dst);
    // aggregation via tf32 HMMA + fused residual relu (256 blocks x 256 thr)
    agg_kernel<<<dim3(8, 4, Bx), 256>>>(Q, out);
}